// round 4
// baseline (speedup 1.0000x reference)
#include <cuda_runtime.h>
#include <cuda_bf16.h>
#include <cstdint>
#include <cstddef>

#define N_CLASS 8192
#define FEAT    1024
#define BATCH   1024

#define TM 128
#define TN 128
#define TK 64
#define KTILES (FEAT / TK)        // 16
#define STAGES 3
#define A_BYTES (TM * 128)        // 16 KB (128 rows x 128B)
#define B_BYTES (TN * 128)        // 16 KB
#define STAGE_BYTES (A_BYTES + B_BYTES)
#define SMEM_TOTAL (STAGES * STAGE_BYTES)   // 96 KB

#define NTILE (N_CLASS / TM)                  // 64
#define NTRI  (NTILE * (NTILE + 1) / 2)       // 2080 upper-triangle tiles
#define CAP 32

// ---------------- device scratch (no allocations allowed) ----------------
__device__ __nv_bfloat16 g_protos[(size_t)N_CLASS * FEAT];  // 16 MB bf16 protos
__device__ float         g_rowsum[N_CLASS];
__device__ int           g_cnt[N_CLASS];
__device__ int           g_list[N_CLASS * CAP];
__device__ int           g_active[BATCH];
__device__ int           g_nact;

// ---------------- helpers ----------------
__device__ __forceinline__ uint32_t smem_u32(const void* p) {
    uint32_t a;
    asm("{ .reg .u64 t; cvta.to.shared.u64 t, %1; cvt.u32.u64 %0, t; }" : "=r"(a) : "l"(p));
    return a;
}
__device__ __forceinline__ void ldmatrix_x4(uint32_t& r0, uint32_t& r1,
                                            uint32_t& r2, uint32_t& r3, uint32_t addr) {
    asm volatile("ldmatrix.sync.aligned.m8n8.x4.shared.b16 {%0,%1,%2,%3}, [%4];"
                 : "=r"(r0), "=r"(r1), "=r"(r2), "=r"(r3) : "r"(addr));
}
__device__ __forceinline__ void mma_bf16(float& c0, float& c1, float& c2, float& c3,
                                         uint32_t a0, uint32_t a1, uint32_t a2, uint32_t a3,
                                         uint32_t b0, uint32_t b1) {
    asm volatile(
        "mma.sync.aligned.m16n8k16.row.col.f32.bf16.bf16.f32 "
        "{%0,%1,%2,%3}, {%4,%5,%6,%7}, {%8,%9}, {%0,%1,%2,%3};"
        : "+f"(c0), "+f"(c1), "+f"(c2), "+f"(c3)
        : "r"(a0), "r"(a1), "r"(a2), "r"(a3), "r"(b0), "r"(b1));
}

// ============================================================================
// Kernel 0: group batch samples by label
// ============================================================================
__global__ void __launch_bounds__(1024) group_kernel(const int* __restrict__ labels)
{
    const int t = threadIdx.x;
    #pragma unroll
    for (int i = t; i < N_CLASS; i += 1024) g_cnt[i] = 0;
    if (t == 0) g_nact = 0;
    __syncthreads();
    const int l = labels[t];
    const int pos = atomicAdd(&g_cnt[l], 1);
    if (pos < CAP) g_list[l * CAP + pos] = t;
    if (pos == 0) {
        int a = atomicAdd(&g_nact, 1);
        g_active[a] = l;
    }
}

// ============================================================================
// Kernel 1a: streaming fp32 -> bf16 convert of ALL prototype rows + zero rowsum
// ============================================================================
__global__ void __launch_bounds__(256) convert_kernel(const float* __restrict__ protos)
{
    const int tid = blockIdx.x * 256 + threadIdx.x;
    const int stride = gridDim.x * 256;
    const float4* __restrict__ src = reinterpret_cast<const float4*>(protos);
    __nv_bfloat162* __restrict__ dst = reinterpret_cast<__nv_bfloat162*>(g_protos);
    #pragma unroll 4
    for (int i = tid; i < N_CLASS * FEAT / 4; i += stride) {
        float4 v = src[i];
        dst[2 * i + 0] = __floats2bfloat162_rn(v.x, v.y);
        dst[2 * i + 1] = __floats2bfloat162_rn(v.z, v.w);
    }
    if (tid < N_CLASS) g_rowsum[tid] = 0.0f;
}

// ============================================================================
// Kernel 1b: sequential EMA chain for ACTIVE classes only
// ============================================================================
__global__ void __launch_bounds__(256) ema_active_kernel(
    const float* __restrict__ protos,
    const float* __restrict__ feats)
{
    __shared__ int   s_idx[CAP];
    __shared__ float s_red[8];
    __shared__ int   s_c;

    const int t = threadIdx.x;
    if (t == 0) s_c = (blockIdx.x < g_nact) ? g_active[blockIdx.x] : -1;
    __syncthreads();
    const int c = s_c;
    if (c < 0) return;

    const int cnt = min(g_cnt[c], CAP);
    if (t == 0) {
        for (int m = 0; m < cnt; m++) s_idx[m] = g_list[c * CAP + m];
        for (int a = 1; a < cnt; a++) {
            int v = s_idx[a], b = a - 1;
            while (b >= 0 && s_idx[b] > v) { s_idx[b + 1] = s_idx[b]; b--; }
            s_idx[b + 1] = v;
        }
    }
    __syncthreads();

    float4 r = reinterpret_cast<const float4*>(protos)[(size_t)c * (FEAT / 4) + t];
    for (int m = 0; m < cnt; m++) {
        const int i = s_idx[m];
        float4 f = reinterpret_cast<const float4*>(feats)[(size_t)i * (FEAT / 4) + t];
        r.x = r.x * 0.95f + 0.05f * f.x;
        r.y = r.y * 0.95f + 0.05f * f.y;
        r.z = r.z * 0.95f + 0.05f * f.z;
        r.w = r.w * 0.95f + 0.05f * f.w;
        float ss = r.x * r.x + r.y * r.y + r.z * r.z + r.w * r.w;
        #pragma unroll
        for (int o = 16; o > 0; o >>= 1) ss += __shfl_xor_sync(0xffffffffu, ss, o);
        if ((t & 31) == 0) s_red[t >> 5] = ss;
        __syncthreads();
        float tot = s_red[0] + s_red[1] + s_red[2] + s_red[3]
                  + s_red[4] + s_red[5] + s_red[6] + s_red[7];
        float inv = 1.0f / fmaxf(sqrtf(tot), 1e-12f);
        r.x *= inv; r.y *= inv; r.z *= inv; r.w *= inv;
        __syncthreads();
    }

    __nv_bfloat162* dst =
        reinterpret_cast<__nv_bfloat162*>(g_protos + (size_t)c * FEAT + (size_t)t * 4);
    dst[0] = __floats2bfloat162_rn(r.x, r.y);
    dst[1] = __floats2bfloat162_rn(r.z, r.w);
}

// ============================================================================
// Kernel 2: fused symmetric Gram GEMM + exp + row/col sums
// 128x128 CTA tile, 4 warps (warp tile 64x64), 3-stage cp.async pipeline.
// ============================================================================
__global__ void __launch_bounds__(128, 2) gemm_exp_kernel()
{
    // decode linear id -> upper-triangle (ti, tj), row-major
    const int id = blockIdx.x;
    int ti = (int)((2.0f * NTILE + 1.0f
                    - sqrtf((2.0f * NTILE + 1.0f) * (2.0f * NTILE + 1.0f) - 8.0f * id))
                   * 0.5f);
    while ((ti + 1) * NTILE - ((ti + 1) * ti) / 2 <= id) ti++;
    while (ti * NTILE - (ti * (ti - 1)) / 2 > id) ti--;
    const int tj = ti + (id - (ti * NTILE - (ti * (ti - 1)) / 2));

    const bool diag   = (ti == tj);
    const int rowBase = ti * TM;
    const int colBase = tj * TN;

    extern __shared__ __align__(1024) char smem[];
    const uint32_t sb = smem_u32(smem);

    const int t   = threadIdx.x;          // 0..127
    const int wid = t >> 5;               // 0..3
    const int lid = t & 31;
    const int wr  = wid >> 1;             // 0..1 : 64-row half
    const int wc  = wid & 1;              // 0..1 : 64-col half

    const __nv_bfloat16* __restrict__ P = g_protos;

    // ---- loader: per-thread constant-stride walk (16 chunks of 16B) ----
    const int kc = t & 7;                 // 16B chunk within 128B row
    const int r0 = t >> 3;                // base row 0..15
    const uint32_t dOffA = r0 * 128 + ((kc ^ (r0 & 7)) << 4);
    const __nv_bfloat16* pA0 = P + (size_t)(rowBase + r0) * FEAT + kc * 8;
    const __nv_bfloat16* pB0 = P + (size_t)(colBase + r0) * FEAT + kc * 8;

    auto load_stage = [&](int slot, int kt) {
        const uint32_t dA = sb + slot * STAGE_BYTES + dOffA;
        const __nv_bfloat16* sA = pA0 + kt * TK;
        const __nv_bfloat16* sB = pB0 + kt * TK;
        #pragma unroll
        for (int q = 0; q < 8; q++) {
            asm volatile("cp.async.cg.shared.global [%0], [%1], 16;"
                         :: "r"(dA + q * 2048), "l"(sA + (size_t)q * 16 * FEAT));
            asm volatile("cp.async.cg.shared.global [%0], [%1], 16;"
                         :: "r"(dA + A_BYTES + q * 2048), "l"(sB + (size_t)q * 16 * FEAT));
        }
        asm volatile("cp.async.commit_group;" ::: "memory");
    };

    load_stage(0, 0);
    load_stage(1, 1);

    float acc[4][8][4];
    #pragma unroll
    for (int mf = 0; mf < 4; mf++)
        #pragma unroll
        for (int nf = 0; nf < 8; nf++)
            #pragma unroll
            for (int e = 0; e < 4; e++) acc[mf][nf][e] = 0.0f;

    const int lmod16 = lid & 15;
    const int ldiv16 = lid >> 4;
    const int xsw    = lmod16 & 7;        // row&7 for ALL ldsm rows of this lane
    // row offsets (constant per thread)
    uint32_t aOff[4], bOff[4];
    #pragma unroll
    for (int mf = 0; mf < 4; mf++) aOff[mf] = (wr * 64 + mf * 16 + lmod16) * 128;
    #pragma unroll
    for (int np = 0; np < 4; np++) bOff[np] = (wc * 64 + np * 16 + lmod16) * 128;

    for (int kt = 0; kt < KTILES; kt++) {
        asm volatile("cp.async.wait_group %0;" :: "n"(STAGES - 2) : "memory");
        __syncthreads();
        if (kt + STAGES - 1 < KTILES) load_stage((kt + STAGES - 1) % STAGES, kt + STAGES - 1);
        else asm volatile("cp.async.commit_group;" ::: "memory");

        const uint32_t Abase = sb + (kt % STAGES) * STAGE_BYTES;
        const uint32_t Bbase = Abase + A_BYTES;

        #pragma unroll
        for (int ks = 0; ks < TK / 16; ks++) {
            const uint32_t sw = (uint32_t)(((ks * 2 + ldiv16) ^ xsw) << 4);

            uint32_t a[4][4];
            #pragma unroll
            for (int mf = 0; mf < 4; mf++)
                ldmatrix_x4(a[mf][0], a[mf][1], a[mf][2], a[mf][3],
                            Abase + aOff[mf] + sw);
            uint32_t b[8][2];
            #pragma unroll
            for (int np = 0; np < 4; np++) {
                uint32_t q0, q1, q2, q3;
                ldmatrix_x4(q0, q1, q2, q3, Bbase + bOff[np] + sw);
                b[np * 2 + 0][0] = q0; b[np * 2 + 0][1] = q2;
                b[np * 2 + 1][0] = q1; b[np * 2 + 1][1] = q3;
            }
            #pragma unroll
            for (int mf = 0; mf < 4; mf++)
                #pragma unroll
                for (int nf = 0; nf < 8; nf++)
                    mma_bf16(acc[mf][nf][0], acc[mf][nf][1],
                             acc[mf][nf][2], acc[mf][nf][3],
                             a[mf][0], a[mf][1], a[mf][2], a[mf][3],
                             b[nf][0], b[nf][1]);
        }
    }
    asm volatile("cp.async.wait_group 0;" ::: "memory");

    // ---- epilogue: exp(10*x), row sums + (off-diag) butterfly column sums ----
    float* srow = reinterpret_cast<float*>(smem);        // [128]
    float* scol = srow + 128;                            // [128]
    __syncthreads();
    srow[t] = 0.0f;
    srow[t + 128] = 0.0f;
    __syncthreads();

    const int g  = lid >> 2;
    const int tg = lid & 3;

    float cs[8][2];
    #pragma unroll
    for (int nf = 0; nf < 8; nf++) { cs[nf][0] = 0.0f; cs[nf][1] = 0.0f; }

    #pragma unroll
    for (int mf = 0; mf < 4; mf++) {
        float rs0 = 0.0f, rs1 = 0.0f;
        const int gr0 = rowBase + wr * 64 + mf * 16 + g;
        const int gr1 = gr0 + 8;
        #pragma unroll
        for (int nf = 0; nf < 8; nf++) {
            float e0 = __expf(acc[mf][nf][0] * 10.0f);
            float e1 = __expf(acc[mf][nf][1] * 10.0f);
            float e2 = __expf(acc[mf][nf][2] * 10.0f);
            float e3 = __expf(acc[mf][nf][3] * 10.0f);
            if (diag) {
                const int gc0 = colBase + wc * 64 + nf * 8 + 2 * tg;
                const int gc1 = gc0 + 1;
                if (gr0 == gc0) e0 = 0.0f;
                if (gr0 == gc1) e1 = 0.0f;
                if (gr1 == gc0) e2 = 0.0f;
                if (gr1 == gc1) e3 = 0.0f;
            }
            rs0 += e0 + e1;
            rs1 += e2 + e3;
            cs[nf][0] += e0 + e2;
            cs[nf][1] += e1 + e3;
        }
        rs0 += __shfl_xor_sync(0xffffffffu, rs0, 1);
        rs0 += __shfl_xor_sync(0xffffffffu, rs0, 2);
        rs1 += __shfl_xor_sync(0xffffffffu, rs1, 1);
        rs1 += __shfl_xor_sync(0xffffffffu, rs1, 2);
        if (tg == 0) {
            atomicAdd(&srow[wr * 64 + mf * 16 + g],     rs0);
            atomicAdd(&srow[wr * 64 + mf * 16 + g + 8], rs1);
        }
    }
    if (!diag) {
        #pragma unroll
        for (int nf = 0; nf < 8; nf++) {
            #pragma unroll
            for (int h = 0; h < 2; h++) {
                float v = cs[nf][h];
                v += __shfl_xor_sync(0xffffffffu, v, 4);
                v += __shfl_xor_sync(0xffffffffu, v, 8);
                v += __shfl_xor_sync(0xffffffffu, v, 16);
                if (g == 0)
                    atomicAdd(&scol[wc * 64 + nf * 8 + 2 * tg + h], v);
            }
        }
    }
    __syncthreads();
    atomicAdd(&g_rowsum[rowBase + t], srow[t]);
    if (!diag) atomicAdd(&g_rowsum[colBase + t], scol[t]);
}

// ============================================================================
// Kernel 3: loss = mean(log(rowsum / (C-1)))
// ============================================================================
__global__ void __launch_bounds__(256) finalize_kernel(float* __restrict__ out)
{
    const int t = threadIdx.x;
    float acc = 0.0f;
    for (int i = t; i < N_CLASS; i += 256)
        acc += logf(g_rowsum[i] * (1.0f / (float)(N_CLASS - 1)));
    #pragma unroll
    for (int o = 16; o > 0; o >>= 1) acc += __shfl_xor_sync(0xffffffffu, acc, o);
    __shared__ float s[8];
    if ((t & 31) == 0) s[t >> 5] = acc;
    __syncthreads();
    if (t == 0) {
        float v = s[0] + s[1] + s[2] + s[3] + s[4] + s[5] + s[6] + s[7];
        out[0] = v / (float)N_CLASS;
    }
}

// ============================================================================
extern "C" void kernel_launch(void* const* d_in, const int* in_sizes, int n_in,
                              void* d_out, int out_size)
{
    const float* features   = nullptr;
    const int*   labels     = nullptr;
    const float* prototypes = nullptr;
    for (int k = 0; k < n_in; k++) {
        if      (in_sizes[k] == BATCH)          labels     = (const int*)d_in[k];
        else if (in_sizes[k] == BATCH * FEAT)   features   = (const float*)d_in[k];
        else if (in_sizes[k] == N_CLASS * FEAT) prototypes = (const float*)d_in[k];
    }
    float* out = (float*)d_out;

    static bool attr_done = false;
    if (!attr_done) {
        cudaFuncSetAttribute(gemm_exp_kernel,
                             cudaFuncAttributeMaxDynamicSharedMemorySize, SMEM_TOTAL);
        attr_done = true;
    }

    group_kernel<<<1, 1024>>>(labels);
    convert_kernel<<<512, 256>>>(prototypes);
    ema_active_kernel<<<BATCH, 256>>>(prototypes, features);
    gemm_exp_kernel<<<NTRI, 128, SMEM_TOTAL>>>();
    finalize_kernel<<<1, 256>>>(out);
    (void)out_size;
}

// round 5
// speedup vs baseline: 1.0011x; 1.0011x over previous
#include <cuda_runtime.h>
#include <cuda_bf16.h>
#include <cstdint>
#include <cstddef>

#define N_CLASS 8192
#define FEAT    1024
#define BATCH   1024

#define TM 128
#define TN 128
#define TK 64
#define KTILES (FEAT / TK)        // 16
#define STAGES 3
#define A_BYTES (TM * 128)        // 16 KB (128 rows x 128B)
#define B_BYTES (TN * 128)        // 16 KB
#define STAGE_BYTES (A_BYTES + B_BYTES)
#define SMEM_TOTAL (STAGES * STAGE_BYTES)   // 96 KB

#define NTILE (N_CLASS / TM)                  // 64
#define NTRI  (NTILE * (NTILE + 1) / 2)       // 2080 upper-triangle tiles
#define CAP 32

// ---------------- device scratch (no allocations allowed) ----------------
__device__ __nv_bfloat16 g_protos[(size_t)N_CLASS * FEAT];  // 16 MB bf16 protos
__device__ float         g_rowsum[N_CLASS];
__device__ int           g_cnt[N_CLASS];
__device__ int           g_list[N_CLASS * CAP];
__device__ int           g_active[BATCH];
__device__ int           g_nact;

// ---------------- helpers ----------------
__device__ __forceinline__ uint32_t smem_u32(const void* p) {
    uint32_t a;
    asm("{ .reg .u64 t; cvta.to.shared.u64 t, %1; cvt.u32.u64 %0, t; }" : "=r"(a) : "l"(p));
    return a;
}
__device__ __forceinline__ void ldmatrix_x4(uint32_t& r0, uint32_t& r1,
                                            uint32_t& r2, uint32_t& r3, uint32_t addr) {
    asm volatile("ldmatrix.sync.aligned.m8n8.x4.shared.b16 {%0,%1,%2,%3}, [%4];"
                 : "=r"(r0), "=r"(r1), "=r"(r2), "=r"(r3) : "r"(addr));
}
__device__ __forceinline__ void mma_bf16(float& c0, float& c1, float& c2, float& c3,
                                         uint32_t a0, uint32_t a1, uint32_t a2, uint32_t a3,
                                         uint32_t b0, uint32_t b1) {
    asm volatile(
        "mma.sync.aligned.m16n8k16.row.col.f32.bf16.bf16.f32 "
        "{%0,%1,%2,%3}, {%4,%5,%6,%7}, {%8,%9}, {%0,%1,%2,%3};"
        : "+f"(c0), "+f"(c1), "+f"(c2), "+f"(c3)
        : "r"(a0), "r"(a1), "r"(a2), "r"(a3), "r"(b0), "r"(b1));
}

// ============================================================================
// Kernel 0: group batch samples by label
// ============================================================================
__global__ void __launch_bounds__(1024) group_kernel(const int* __restrict__ labels)
{
    const int t = threadIdx.x;
    #pragma unroll
    for (int i = t; i < N_CLASS; i += 1024) g_cnt[i] = 0;
    if (t == 0) g_nact = 0;
    __syncthreads();
    const int l = labels[t];
    const int pos = atomicAdd(&g_cnt[l], 1);
    if (pos < CAP) g_list[l * CAP + pos] = t;
    if (pos == 0) {
        int a = atomicAdd(&g_nact, 1);
        g_active[a] = l;
    }
}

// ============================================================================
// Kernel 1a: streaming fp32 -> bf16 convert of ALL prototype rows + zero rowsum
// ============================================================================
__global__ void __launch_bounds__(256) convert_kernel(const float* __restrict__ protos)
{
    const int tid = blockIdx.x * 256 + threadIdx.x;
    const int stride = gridDim.x * 256;
    const float4* __restrict__ src = reinterpret_cast<const float4*>(protos);
    __nv_bfloat162* __restrict__ dst = reinterpret_cast<__nv_bfloat162*>(g_protos);
    #pragma unroll 4
    for (int i = tid; i < N_CLASS * FEAT / 4; i += stride) {
        float4 v = src[i];
        dst[2 * i + 0] = __floats2bfloat162_rn(v.x, v.y);
        dst[2 * i + 1] = __floats2bfloat162_rn(v.z, v.w);
    }
    if (tid < N_CLASS) g_rowsum[tid] = 0.0f;
}

// ============================================================================
// Kernel 1b: sequential EMA chain for ACTIVE classes only
// ============================================================================
__global__ void __launch_bounds__(256) ema_active_kernel(
    const float* __restrict__ protos,
    const float* __restrict__ feats)
{
    __shared__ int   s_idx[CAP];
    __shared__ float s_red[8];
    __shared__ int   s_c;

    const int t = threadIdx.x;
    if (t == 0) s_c = (blockIdx.x < g_nact) ? g_active[blockIdx.x] : -1;
    __syncthreads();
    const int c = s_c;
    if (c < 0) return;

    const int cnt = min(g_cnt[c], CAP);
    if (t == 0) {
        for (int m = 0; m < cnt; m++) s_idx[m] = g_list[c * CAP + m];
        for (int a = 1; a < cnt; a++) {
            int v = s_idx[a], b = a - 1;
            while (b >= 0 && s_idx[b] > v) { s_idx[b + 1] = s_idx[b]; b--; }
            s_idx[b + 1] = v;
        }
    }
    __syncthreads();

    float4 r = reinterpret_cast<const float4*>(protos)[(size_t)c * (FEAT / 4) + t];
    for (int m = 0; m < cnt; m++) {
        const int i = s_idx[m];
        float4 f = reinterpret_cast<const float4*>(feats)[(size_t)i * (FEAT / 4) + t];
        r.x = r.x * 0.95f + 0.05f * f.x;
        r.y = r.y * 0.95f + 0.05f * f.y;
        r.z = r.z * 0.95f + 0.05f * f.z;
        r.w = r.w * 0.95f + 0.05f * f.w;
        float ss = r.x * r.x + r.y * r.y + r.z * r.z + r.w * r.w;
        #pragma unroll
        for (int o = 16; o > 0; o >>= 1) ss += __shfl_xor_sync(0xffffffffu, ss, o);
        if ((t & 31) == 0) s_red[t >> 5] = ss;
        __syncthreads();
        float tot = s_red[0] + s_red[1] + s_red[2] + s_red[3]
                  + s_red[4] + s_red[5] + s_red[6] + s_red[7];
        float inv = 1.0f / fmaxf(sqrtf(tot), 1e-12f);
        r.x *= inv; r.y *= inv; r.z *= inv; r.w *= inv;
        __syncthreads();
    }

    __nv_bfloat162* dst =
        reinterpret_cast<__nv_bfloat162*>(g_protos + (size_t)c * FEAT + (size_t)t * 4);
    dst[0] = __floats2bfloat162_rn(r.x, r.y);
    dst[1] = __floats2bfloat162_rn(r.z, r.w);
}

// ============================================================================
// Kernel 2: fused symmetric Gram GEMM + exp + row/col sums
// 128x128 CTA tile, 4 warps (warp tile 64x64), 3-stage cp.async pipeline,
// register-fragment double buffering to hide LDSM latency under MMAs.
// ============================================================================
__global__ void __launch_bounds__(128, 2) gemm_exp_kernel()
{
    // decode linear id -> upper-triangle (ti, tj), row-major
    const int id = blockIdx.x;
    int ti = (int)((2.0f * NTILE + 1.0f
                    - sqrtf((2.0f * NTILE + 1.0f) * (2.0f * NTILE + 1.0f) - 8.0f * id))
                   * 0.5f);
    while ((ti + 1) * NTILE - ((ti + 1) * ti) / 2 <= id) ti++;
    while (ti * NTILE - (ti * (ti - 1)) / 2 > id) ti--;
    const int tj = ti + (id - (ti * NTILE - (ti * (ti - 1)) / 2));

    const bool diag   = (ti == tj);
    const int rowBase = ti * TM;
    const int colBase = tj * TN;

    extern __shared__ __align__(1024) char smem[];
    const uint32_t sb = smem_u32(smem);

    const int t   = threadIdx.x;          // 0..127
    const int wid = t >> 5;               // 0..3
    const int lid = t & 31;
    const int wr  = wid >> 1;             // 0..1 : 64-row half
    const int wc  = wid & 1;              // 0..1 : 64-col half

    const __nv_bfloat16* __restrict__ P = g_protos;

    // ---- loader: per-thread constant-stride walk (16 chunks of 16B) ----
    const int kc = t & 7;
    const int r0 = t >> 3;
    const uint32_t dOffA = r0 * 128 + ((kc ^ (r0 & 7)) << 4);
    const __nv_bfloat16* pA0 = P + (size_t)(rowBase + r0) * FEAT + kc * 8;
    const __nv_bfloat16* pB0 = P + (size_t)(colBase + r0) * FEAT + kc * 8;

    auto load_stage = [&](int slot, int kt) {
        const uint32_t dA = sb + slot * STAGE_BYTES + dOffA;
        const __nv_bfloat16* sA = pA0 + kt * TK;
        const __nv_bfloat16* sB = pB0 + kt * TK;
        #pragma unroll
        for (int q = 0; q < 8; q++) {
            asm volatile("cp.async.cg.shared.global [%0], [%1], 16;"
                         :: "r"(dA + q * 2048), "l"(sA + (size_t)q * 16 * FEAT));
            asm volatile("cp.async.cg.shared.global [%0], [%1], 16;"
                         :: "r"(dA + A_BYTES + q * 2048), "l"(sB + (size_t)q * 16 * FEAT));
        }
        asm volatile("cp.async.commit_group;" ::: "memory");
    };

    load_stage(0, 0);
    load_stage(1, 1);

    float acc[4][8][4];
    #pragma unroll
    for (int mf = 0; mf < 4; mf++)
        #pragma unroll
        for (int nf = 0; nf < 8; nf++)
            #pragma unroll
            for (int e = 0; e < 4; e++) acc[mf][nf][e] = 0.0f;

    const int lmod16 = lid & 15;
    const int ldiv16 = lid >> 4;
    const int xsw    = lmod16 & 7;
    uint32_t aOff[4], bOff[4];
    #pragma unroll
    for (int mf = 0; mf < 4; mf++) aOff[mf] = (wr * 64 + mf * 16 + lmod16) * 128;
    #pragma unroll
    for (int np = 0; np < 4; np++) bOff[np] = (wc * 64 + np * 16 + lmod16) * 128;

    // double-buffered register fragments
    uint32_t a[2][4][4];
    uint32_t b[2][8][2];

    auto ldfrag = [&](int buf, int ks, uint32_t Abase, uint32_t Bbase) {
        const uint32_t sw = (uint32_t)(((ks * 2 + ldiv16) ^ xsw) << 4);
        #pragma unroll
        for (int mf = 0; mf < 4; mf++)
            ldmatrix_x4(a[buf][mf][0], a[buf][mf][1], a[buf][mf][2], a[buf][mf][3],
                        Abase + aOff[mf] + sw);
        #pragma unroll
        for (int np = 0; np < 4; np++) {
            uint32_t q0, q1, q2, q3;
            ldmatrix_x4(q0, q1, q2, q3, Bbase + bOff[np] + sw);
            b[buf][np * 2 + 0][0] = q0; b[buf][np * 2 + 0][1] = q2;
            b[buf][np * 2 + 1][0] = q1; b[buf][np * 2 + 1][1] = q3;
        }
    };

    for (int kt = 0; kt < KTILES; kt++) {
        asm volatile("cp.async.wait_group %0;" :: "n"(STAGES - 2) : "memory");
        __syncthreads();
        if (kt + STAGES - 1 < KTILES) load_stage((kt + STAGES - 1) % STAGES, kt + STAGES - 1);
        else asm volatile("cp.async.commit_group;" ::: "memory");

        const uint32_t Abase = sb + (kt % STAGES) * STAGE_BYTES;
        const uint32_t Bbase = Abase + A_BYTES;

        ldfrag(0, 0, Abase, Bbase);
        #pragma unroll
        for (int ks = 0; ks < TK / 16; ks++) {
            const int cur = ks & 1;
            if (ks < TK / 16 - 1) ldfrag(cur ^ 1, ks + 1, Abase, Bbase);
            #pragma unroll
            for (int mf = 0; mf < 4; mf++)
                #pragma unroll
                for (int nf = 0; nf < 8; nf++)
                    mma_bf16(acc[mf][nf][0], acc[mf][nf][1],
                             acc[mf][nf][2], acc[mf][nf][3],
                             a[cur][mf][0], a[cur][mf][1], a[cur][mf][2], a[cur][mf][3],
                             b[cur][nf][0], b[cur][nf][1]);
        }
    }
    asm volatile("cp.async.wait_group 0;" ::: "memory");

    // ---- epilogue: exp(10*x), row sums + (off-diag) butterfly column sums ----
    float* srow = reinterpret_cast<float*>(smem);        // [128]
    float* scol = srow + 128;                            // [128]
    __syncthreads();
    srow[t] = 0.0f;
    srow[t + 128] = 0.0f;
    __syncthreads();

    const int g  = lid >> 2;
    const int tg = lid & 3;

    float cs[8][2];
    #pragma unroll
    for (int nf = 0; nf < 8; nf++) { cs[nf][0] = 0.0f; cs[nf][1] = 0.0f; }

    #pragma unroll
    for (int mf = 0; mf < 4; mf++) {
        float rs0 = 0.0f, rs1 = 0.0f;
        const int gr0 = rowBase + wr * 64 + mf * 16 + g;
        const int gr1 = gr0 + 8;
        #pragma unroll
        for (int nf = 0; nf < 8; nf++) {
            float e0 = __expf(acc[mf][nf][0] * 10.0f);
            float e1 = __expf(acc[mf][nf][1] * 10.0f);
            float e2 = __expf(acc[mf][nf][2] * 10.0f);
            float e3 = __expf(acc[mf][nf][3] * 10.0f);
            if (diag) {
                const int gc0 = colBase + wc * 64 + nf * 8 + 2 * tg;
                const int gc1 = gc0 + 1;
                if (gr0 == gc0) e0 = 0.0f;
                if (gr0 == gc1) e1 = 0.0f;
                if (gr1 == gc0) e2 = 0.0f;
                if (gr1 == gc1) e3 = 0.0f;
            }
            rs0 += e0 + e1;
            rs1 += e2 + e3;
            cs[nf][0] += e0 + e2;
            cs[nf][1] += e1 + e3;
        }
        rs0 += __shfl_xor_sync(0xffffffffu, rs0, 1);
        rs0 += __shfl_xor_sync(0xffffffffu, rs0, 2);
        rs1 += __shfl_xor_sync(0xffffffffu, rs1, 1);
        rs1 += __shfl_xor_sync(0xffffffffu, rs1, 2);
        if (tg == 0) {
            atomicAdd(&srow[wr * 64 + mf * 16 + g],     rs0);
            atomicAdd(&srow[wr * 64 + mf * 16 + g + 8], rs1);
        }
    }
    if (!diag) {
        #pragma unroll
        for (int nf = 0; nf < 8; nf++) {
            #pragma unroll
            for (int h = 0; h < 2; h++) {
                float v = cs[nf][h];
                v += __shfl_xor_sync(0xffffffffu, v, 4);
                v += __shfl_xor_sync(0xffffffffu, v, 8);
                v += __shfl_xor_sync(0xffffffffu, v, 16);
                if (g == 0)
                    atomicAdd(&scol[wc * 64 + nf * 8 + 2 * tg + h], v);
            }
        }
    }
    __syncthreads();
    atomicAdd(&g_rowsum[rowBase + t], srow[t]);
    if (!diag) atomicAdd(&g_rowsum[colBase + t], scol[t]);
}

// ============================================================================
// Kernel 3: loss = mean(log(rowsum / (C-1)))
// ============================================================================
__global__ void __launch_bounds__(256) finalize_kernel(float* __restrict__ out)
{
    const int t = threadIdx.x;
    float acc = 0.0f;
    for (int i = t; i < N_CLASS; i += 256)
        acc += logf(g_rowsum[i] * (1.0f / (float)(N_CLASS - 1)));
    #pragma unroll
    for (int o = 16; o > 0; o >>= 1) acc += __shfl_xor_sync(0xffffffffu, acc, o);
    __shared__ float s[8];
    if ((t & 31) == 0) s[t >> 5] = acc;
    __syncthreads();
    if (t == 0) {
        float v = s[0] + s[1] + s[2] + s[3] + s[4] + s[5] + s[6] + s[7];
        out[0] = v / (float)N_CLASS;
    }
}

// ============================================================================
extern "C" void kernel_launch(void* const* d_in, const int* in_sizes, int n_in,
                              void* d_out, int out_size)
{
    const float* features   = nullptr;
    const int*   labels     = nullptr;
    const float* prototypes = nullptr;
    for (int k = 0; k < n_in; k++) {
        if      (in_sizes[k] == BATCH)          labels     = (const int*)d_in[k];
        else if (in_sizes[k] == BATCH * FEAT)   features   = (const float*)d_in[k];
        else if (in_sizes[k] == N_CLASS * FEAT) prototypes = (const float*)d_in[k];
    }
    float* out = (float*)d_out;

    static bool attr_done = false;
    if (!attr_done) {
        cudaFuncSetAttribute(gemm_exp_kernel,
                             cudaFuncAttributeMaxDynamicSharedMemorySize, SMEM_TOTAL);
        attr_done = true;
    }

    group_kernel<<<1, 1024>>>(labels);
    convert_kernel<<<512, 256>>>(prototypes);
    ema_active_kernel<<<BATCH, 256>>>(prototypes, features);
    gemm_exp_kernel<<<NTRI, 128, SMEM_TOTAL>>>();
    finalize_kernel<<<1, 256>>>(out);
    (void)out_size;
}

// round 6
// speedup vs baseline: 1.0318x; 1.0307x over previous
#include <cuda_runtime.h>
#include <cuda_fp16.h>
#include <cstdint>
#include <cstddef>

#define N_CLASS 8192
#define FEAT    1024
#define BATCH   1024

#define TM 128
#define TN 128
#define TK 64
#define KTILES (FEAT / TK)        // 16
#define STAGES 3
#define A_BYTES (TM * 128)        // 16 KB (128 rows x 128B)
#define B_BYTES (TN * 128)        // 16 KB
#define STAGE_BYTES (A_BYTES + B_BYTES)
#define SMEM_TOTAL (STAGES * STAGE_BYTES)   // 96 KB

#define NTILE (N_CLASS / TM)                  // 64
#define NTRI  (NTILE * (NTILE + 1) / 2)       // 2080 upper-triangle tiles
#define CAP 32

// ---------------- device scratch (no allocations allowed) ----------------
__device__ __half g_protos[(size_t)N_CLASS * FEAT];  // 16 MB fp16 protos
__device__ float  g_rowsum[N_CLASS];
__device__ int    g_cnt[N_CLASS];
__device__ int    g_list[N_CLASS * CAP];
__device__ int    g_active[BATCH];
__device__ int    g_nact;

// ---------------- helpers ----------------
__device__ __forceinline__ uint32_t smem_u32(const void* p) {
    uint32_t a;
    asm("{ .reg .u64 t; cvta.to.shared.u64 t, %1; cvt.u32.u64 %0, t; }" : "=r"(a) : "l"(p));
    return a;
}
__device__ __forceinline__ void ldmatrix_x4(uint32_t& r0, uint32_t& r1,
                                            uint32_t& r2, uint32_t& r3, uint32_t addr) {
    asm volatile("ldmatrix.sync.aligned.m8n8.x4.shared.b16 {%0,%1,%2,%3}, [%4];"
                 : "=r"(r0), "=r"(r1), "=r"(r2), "=r"(r3) : "r"(addr));
}
// fp16-accumulator HMMA: D/C packed as two .f16x2 regs
// c0 = {(g,2tg),(g,2tg+1)}, c1 = {(g+8,2tg),(g+8,2tg+1)}
__device__ __forceinline__ void mma_f16acc(uint32_t& c0, uint32_t& c1,
                                           uint32_t a0, uint32_t a1, uint32_t a2, uint32_t a3,
                                           uint32_t b0, uint32_t b1) {
    asm volatile(
        "mma.sync.aligned.m16n8k16.row.col.f16.f16.f16.f16 "
        "{%0,%1}, {%2,%3,%4,%5}, {%6,%7}, {%0,%1};"
        : "+r"(c0), "+r"(c1)
        : "r"(a0), "r"(a1), "r"(a2), "r"(a3), "r"(b0), "r"(b1));
}

// ============================================================================
// Kernel 0: group batch samples by label
// ============================================================================
__global__ void __launch_bounds__(1024) group_kernel(const int* __restrict__ labels)
{
    const int t = threadIdx.x;
    #pragma unroll
    for (int i = t; i < N_CLASS; i += 1024) g_cnt[i] = 0;
    if (t == 0) g_nact = 0;
    __syncthreads();
    const int l = labels[t];
    const int pos = atomicAdd(&g_cnt[l], 1);
    if (pos < CAP) g_list[l * CAP + pos] = t;
    if (pos == 0) {
        int a = atomicAdd(&g_nact, 1);
        g_active[a] = l;
    }
}

// ============================================================================
// Kernel 1a: streaming fp32 -> fp16 convert of ALL prototype rows + zero rowsum
// ============================================================================
__global__ void __launch_bounds__(256) convert_kernel(const float* __restrict__ protos)
{
    const int tid = blockIdx.x * 256 + threadIdx.x;
    const int stride = gridDim.x * 256;
    const float4* __restrict__ src = reinterpret_cast<const float4*>(protos);
    __half2* __restrict__ dst = reinterpret_cast<__half2*>(g_protos);
    #pragma unroll 4
    for (int i = tid; i < N_CLASS * FEAT / 4; i += stride) {
        float4 v = src[i];
        dst[2 * i + 0] = __floats2half2_rn(v.x, v.y);
        dst[2 * i + 1] = __floats2half2_rn(v.z, v.w);
    }
    if (tid < N_CLASS) g_rowsum[tid] = 0.0f;
}

// ============================================================================
// Kernel 1b: sequential EMA chain for ACTIVE classes only
// ============================================================================
__global__ void __launch_bounds__(256) ema_active_kernel(
    const float* __restrict__ protos,
    const float* __restrict__ feats)
{
    __shared__ int   s_idx[CAP];
    __shared__ float s_red[8];
    __shared__ int   s_c;

    const int t = threadIdx.x;
    if (t == 0) s_c = (blockIdx.x < g_nact) ? g_active[blockIdx.x] : -1;
    __syncthreads();
    const int c = s_c;
    if (c < 0) return;

    const int cnt = min(g_cnt[c], CAP);
    if (t == 0) {
        for (int m = 0; m < cnt; m++) s_idx[m] = g_list[c * CAP + m];
        for (int a = 1; a < cnt; a++) {
            int v = s_idx[a], b = a - 1;
            while (b >= 0 && s_idx[b] > v) { s_idx[b + 1] = s_idx[b]; b--; }
            s_idx[b + 1] = v;
        }
    }
    __syncthreads();

    float4 r = reinterpret_cast<const float4*>(protos)[(size_t)c * (FEAT / 4) + t];
    for (int m = 0; m < cnt; m++) {
        const int i = s_idx[m];
        float4 f = reinterpret_cast<const float4*>(feats)[(size_t)i * (FEAT / 4) + t];
        r.x = r.x * 0.95f + 0.05f * f.x;
        r.y = r.y * 0.95f + 0.05f * f.y;
        r.z = r.z * 0.95f + 0.05f * f.z;
        r.w = r.w * 0.95f + 0.05f * f.w;
        float ss = r.x * r.x + r.y * r.y + r.z * r.z + r.w * r.w;
        #pragma unroll
        for (int o = 16; o > 0; o >>= 1) ss += __shfl_xor_sync(0xffffffffu, ss, o);
        if ((t & 31) == 0) s_red[t >> 5] = ss;
        __syncthreads();
        float tot = s_red[0] + s_red[1] + s_red[2] + s_red[3]
                  + s_red[4] + s_red[5] + s_red[6] + s_red[7];
        float inv = 1.0f / fmaxf(sqrtf(tot), 1e-12f);
        r.x *= inv; r.y *= inv; r.z *= inv; r.w *= inv;
        __syncthreads();
    }

    __half2* dst = reinterpret_cast<__half2*>(g_protos + (size_t)c * FEAT + (size_t)t * 4);
    dst[0] = __floats2half2_rn(r.x, r.y);
    dst[1] = __floats2half2_rn(r.z, r.w);
}

// ============================================================================
// Kernel 2: fused symmetric Gram GEMM (fp16 in, fp16 acc) + exp + row/col sums
// 128x128 CTA tile, 4 warps (warp tile 64x64), 3-stage cp.async pipeline.
// ============================================================================
__global__ void __launch_bounds__(128, 2) gemm_exp_kernel()
{
    // decode linear id -> upper-triangle (ti, tj), row-major
    const int id = blockIdx.x;
    int ti = (int)((2.0f * NTILE + 1.0f
                    - sqrtf((2.0f * NTILE + 1.0f) * (2.0f * NTILE + 1.0f) - 8.0f * id))
                   * 0.5f);
    while ((ti + 1) * NTILE - ((ti + 1) * ti) / 2 <= id) ti++;
    while (ti * NTILE - (ti * (ti - 1)) / 2 > id) ti--;
    const int tj = ti + (id - (ti * NTILE - (ti * (ti - 1)) / 2));

    const bool diag   = (ti == tj);
    const int rowBase = ti * TM;
    const int colBase = tj * TN;

    extern __shared__ __align__(1024) char smem[];
    const uint32_t sb = smem_u32(smem);

    const int t   = threadIdx.x;          // 0..127
    const int wid = t >> 5;               // 0..3
    const int lid = t & 31;
    const int wr  = wid >> 1;             // 0..1 : 64-row half
    const int wc  = wid & 1;              // 0..1 : 64-col half

    const __half* __restrict__ P = g_protos;

    // ---- loader: per-thread constant-stride walk (16 chunks of 16B) ----
    const int kc = t & 7;
    const int r0 = t >> 3;
    const uint32_t dOffA = r0 * 128 + ((kc ^ (r0 & 7)) << 4);
    const __half* pA0 = P + (size_t)(rowBase + r0) * FEAT + kc * 8;
    const __half* pB0 = P + (size_t)(colBase + r0) * FEAT + kc * 8;

    auto load_stage = [&](int slot, int kt) {
        const uint32_t dA = sb + slot * STAGE_BYTES + dOffA;
        const __half* sA = pA0 + kt * TK;
        const __half* sB = pB0 + kt * TK;
        #pragma unroll
        for (int q = 0; q < 8; q++) {
            asm volatile("cp.async.cg.shared.global [%0], [%1], 16;"
                         :: "r"(dA + q * 2048), "l"(sA + (size_t)q * 16 * FEAT));
            asm volatile("cp.async.cg.shared.global [%0], [%1], 16;"
                         :: "r"(dA + A_BYTES + q * 2048), "l"(sB + (size_t)q * 16 * FEAT));
        }
        asm volatile("cp.async.commit_group;" ::: "memory");
    };

    load_stage(0, 0);
    load_stage(1, 1);

    // fp16x2 accumulators: [mf][nf][0] = rows g, [1] = rows g+8 (cols 2tg,2tg+1)
    uint32_t acc[4][8][2];
    #pragma unroll
    for (int mf = 0; mf < 4; mf++)
        #pragma unroll
        for (int nf = 0; nf < 8; nf++) { acc[mf][nf][0] = 0u; acc[mf][nf][1] = 0u; }

    const int lmod16 = lid & 15;
    const int ldiv16 = lid >> 4;
    const int xsw    = lmod16 & 7;
    uint32_t aOff[4], bOff[4];
    #pragma unroll
    for (int mf = 0; mf < 4; mf++) aOff[mf] = (wr * 64 + mf * 16 + lmod16) * 128;
    #pragma unroll
    for (int np = 0; np < 4; np++) bOff[np] = (wc * 64 + np * 16 + lmod16) * 128;

    uint32_t a[2][4][4];
    uint32_t b[2][8][2];

    auto ldfrag = [&](int buf, int ks, uint32_t Abase, uint32_t Bbase) {
        const uint32_t sw = (uint32_t)(((ks * 2 + ldiv16) ^ xsw) << 4);
        #pragma unroll
        for (int mf = 0; mf < 4; mf++)
            ldmatrix_x4(a[buf][mf][0], a[buf][mf][1], a[buf][mf][2], a[buf][mf][3],
                        Abase + aOff[mf] + sw);
        #pragma unroll
        for (int np = 0; np < 4; np++) {
            uint32_t q0, q1, q2, q3;
            ldmatrix_x4(q0, q1, q2, q3, Bbase + bOff[np] + sw);
            b[buf][np * 2 + 0][0] = q0; b[buf][np * 2 + 0][1] = q2;
            b[buf][np * 2 + 1][0] = q1; b[buf][np * 2 + 1][1] = q3;
        }
    };

    for (int kt = 0; kt < KTILES; kt++) {
        asm volatile("cp.async.wait_group %0;" :: "n"(STAGES - 2) : "memory");
        __syncthreads();
        if (kt + STAGES - 1 < KTILES) load_stage((kt + STAGES - 1) % STAGES, kt + STAGES - 1);
        else asm volatile("cp.async.commit_group;" ::: "memory");

        const uint32_t Abase = sb + (kt % STAGES) * STAGE_BYTES;
        const uint32_t Bbase = Abase + A_BYTES;

        ldfrag(0, 0, Abase, Bbase);
        #pragma unroll
        for (int ks = 0; ks < TK / 16; ks++) {
            const int cur = ks & 1;
            if (ks < TK / 16 - 1) ldfrag(cur ^ 1, ks + 1, Abase, Bbase);
            #pragma unroll
            for (int mf = 0; mf < 4; mf++)
                #pragma unroll
                for (int nf = 0; nf < 8; nf++)
                    mma_f16acc(acc[mf][nf][0], acc[mf][nf][1],
                               a[cur][mf][0], a[cur][mf][1], a[cur][mf][2], a[cur][mf][3],
                               b[cur][nf][0], b[cur][nf][1]);
        }
    }
    asm volatile("cp.async.wait_group 0;" ::: "memory");

    // ---- epilogue: exp(10*x), row sums + (off-diag) butterfly column sums ----
    float* srow = reinterpret_cast<float*>(smem);        // [128]
    float* scol = srow + 128;                            // [128]
    __syncthreads();
    srow[t] = 0.0f;
    srow[t + 128] = 0.0f;
    __syncthreads();

    const int g  = lid >> 2;
    const int tg = lid & 3;

    float cs[8][2];
    #pragma unroll
    for (int nf = 0; nf < 8; nf++) { cs[nf][0] = 0.0f; cs[nf][1] = 0.0f; }

    #pragma unroll
    for (int mf = 0; mf < 4; mf++) {
        float rs0 = 0.0f, rs1 = 0.0f;
        const int gr0 = rowBase + wr * 64 + mf * 16 + g;
        const int gr1 = gr0 + 8;
        #pragma unroll
        for (int nf = 0; nf < 8; nf++) {
            float2 lo = __half22float2(*reinterpret_cast<__half2*>(&acc[mf][nf][0]));
            float2 hi = __half22float2(*reinterpret_cast<__half2*>(&acc[mf][nf][1]));
            float e0 = __expf(lo.x * 10.0f);
            float e1 = __expf(lo.y * 10.0f);
            float e2 = __expf(hi.x * 10.0f);
            float e3 = __expf(hi.y * 10.0f);
            if (diag) {
                const int gc0 = colBase + wc * 64 + nf * 8 + 2 * tg;
                const int gc1 = gc0 + 1;
                if (gr0 == gc0) e0 = 0.0f;
                if (gr0 == gc1) e1 = 0.0f;
                if (gr1 == gc0) e2 = 0.0f;
                if (gr1 == gc1) e3 = 0.0f;
            }
            rs0 += e0 + e1;
            rs1 += e2 + e3;
            cs[nf][0] += e0 + e2;
            cs[nf][1] += e1 + e3;
        }
        rs0 += __shfl_xor_sync(0xffffffffu, rs0, 1);
        rs0 += __shfl_xor_sync(0xffffffffu, rs0, 2);
        rs1 += __shfl_xor_sync(0xffffffffu, rs1, 1);
        rs1 += __shfl_xor_sync(0xffffffffu, rs1, 2);
        if (tg == 0) {
            atomicAdd(&srow[wr * 64 + mf * 16 + g],     rs0);
            atomicAdd(&srow[wr * 64 + mf * 16 + g + 8], rs1);
        }
    }
    if (!diag) {
        #pragma unroll
        for (int nf = 0; nf < 8; nf++) {
            #pragma unroll
            for (int h = 0; h < 2; h++) {
                float v = cs[nf][h];
                v += __shfl_xor_sync(0xffffffffu, v, 4);
                v += __shfl_xor_sync(0xffffffffu, v, 8);
                v += __shfl_xor_sync(0xffffffffu, v, 16);
                if (g == 0)
                    atomicAdd(&scol[wc * 64 + nf * 8 + 2 * tg + h], v);
            }
        }
    }
    __syncthreads();
    atomicAdd(&g_rowsum[rowBase + t], srow[t]);
    if (!diag) atomicAdd(&g_rowsum[colBase + t], scol[t]);
}

// ============================================================================
// Kernel 3: loss = mean(log(rowsum / (C-1)))
// ============================================================================
__global__ void __launch_bounds__(256) finalize_kernel(float* __restrict__ out)
{
    const int t = threadIdx.x;
    float acc = 0.0f;
    for (int i = t; i < N_CLASS; i += 256)
        acc += logf(g_rowsum[i] * (1.0f / (float)(N_CLASS - 1)));
    #pragma unroll
    for (int o = 16; o > 0; o >>= 1) acc += __shfl_xor_sync(0xffffffffu, acc, o);
    __shared__ float s[8];
    if ((t & 31) == 0) s[t >> 5] = acc;
    __syncthreads();
    if (t == 0) {
        float v = s[0] + s[1] + s[2] + s[3] + s[4] + s[5] + s[6] + s[7];
        out[0] = v / (float)N_CLASS;
    }
}

// ============================================================================
extern "C" void kernel_launch(void* const* d_in, const int* in_sizes, int n_in,
                              void* d_out, int out_size)
{
    const float* features   = nullptr;
    const int*   labels     = nullptr;
    const float* prototypes = nullptr;
    for (int k = 0; k < n_in; k++) {
        if      (in_sizes[k] == BATCH)          labels     = (const int*)d_in[k];
        else if (in_sizes[k] == BATCH * FEAT)   features   = (const float*)d_in[k];
        else if (in_sizes[k] == N_CLASS * FEAT) prototypes = (const float*)d_in[k];
    }
    float* out = (float*)d_out;

    static bool attr_done = false;
    if (!attr_done) {
        cudaFuncSetAttribute(gemm_exp_kernel,
                             cudaFuncAttributeMaxDynamicSharedMemorySize, SMEM_TOTAL);
        attr_done = true;
    }

    group_kernel<<<1, 1024>>>(labels);
    convert_kernel<<<512, 256>>>(prototypes);
    ema_active_kernel<<<BATCH, 256>>>(prototypes, features);
    gemm_exp_kernel<<<NTRI, 128, SMEM_TOTAL>>>();
    finalize_kernel<<<1, 256>>>(out);
    (void)out_size;
}

// round 7
// speedup vs baseline: 1.0857x; 1.0522x over previous
#include <cuda_runtime.h>
#include <cuda_fp16.h>
#include <cstdint>
#include <cstddef>

#define N_CLASS 8192
#define FEAT    1024
#define BATCH   1024

#define TM 128
#define TN 128
#define TK 64
#define KTILES (FEAT / TK)        // 16
#define A_BYTES (TM * 128)        // 16 KB (128 rows x 128B)
#define B_BYTES (TN * 128)        // 16 KB
#define STAGE_BYTES (A_BYTES + B_BYTES)   // 32 KB
#define CTRL_OFF (3 * STAGE_BYTES)        // 96 KB
#define SMEM_TOTAL (CTRL_OFF + 128)

#define NTILE (N_CLASS / TM)                  // 64
#define NTRI  (NTILE * (NTILE + 1) / 2)       // 2080 upper-triangle tiles
#define CAP 32

// ---------------- device scratch (no allocations allowed) ----------------
__device__ __half g_protos[(size_t)N_CLASS * FEAT];  // 16 MB fp16 protos
__device__ float  g_rowsum[N_CLASS];
__device__ int    g_cnt[N_CLASS];
__device__ int    g_list[N_CLASS * CAP];
__device__ int    g_active[BATCH];
__device__ int    g_nact;
__device__ int    g_done;

// ---------------- helpers ----------------
__device__ __forceinline__ uint32_t smem_u32(const void* p) {
    uint32_t a;
    asm("{ .reg .u64 t; cvta.to.shared.u64 t, %1; cvt.u32.u64 %0, t; }" : "=r"(a) : "l"(p));
    return a;
}
__device__ __forceinline__ void ldmatrix_x4(uint32_t& r0, uint32_t& r1,
                                            uint32_t& r2, uint32_t& r3, uint32_t addr) {
    asm volatile("ldmatrix.sync.aligned.m8n8.x4.shared.b16 {%0,%1,%2,%3}, [%4];"
                 : "=r"(r0), "=r"(r1), "=r"(r2), "=r"(r3) : "r"(addr));
}
__device__ __forceinline__ void mma_f16acc(uint32_t& c0, uint32_t& c1,
                                           uint32_t a0, uint32_t a1, uint32_t a2, uint32_t a3,
                                           uint32_t b0, uint32_t b1) {
    asm volatile(
        "mma.sync.aligned.m16n8k16.row.col.f16.f16.f16.f16 "
        "{%0,%1}, {%2,%3,%4,%5}, {%6,%7}, {%0,%1};"
        : "+r"(c0), "+r"(c1)
        : "r"(a0), "r"(a1), "r"(a2), "r"(a3), "r"(b0), "r"(b1));
}
__device__ __forceinline__ void mbar_init(uint32_t mbar, uint32_t cnt) {
    asm volatile("mbarrier.init.shared.b64 [%0], %1;" :: "r"(mbar), "r"(cnt) : "memory");
}
__device__ __forceinline__ void mbar_arrive(uint32_t mbar) {
    asm volatile("mbarrier.arrive.shared.b64 _, [%0];" :: "r"(mbar) : "memory");
}
__device__ __forceinline__ void cpasync_arrive(uint32_t mbar) {
    asm volatile("cp.async.mbarrier.arrive.noinc.shared.b64 [%0];" :: "r"(mbar) : "memory");
}
__device__ __forceinline__ void mbar_wait(uint32_t mbar, uint32_t parity) {
    asm volatile(
        "{\n\t.reg .pred P;\n\t"
        "W_%=:\n\t"
        "mbarrier.try_wait.parity.acquire.cta.shared::cta.b64 P, [%0], %1, 0x989680;\n\t"
        "@!P bra W_%=;\n\t}"
        :: "r"(mbar), "r"(parity) : "memory");
}

// ============================================================================
// Kernel 1: fused fp32->fp16 convert (blocks 0..511) + label grouping (block 512)
// ============================================================================
__global__ void __launch_bounds__(256) convert_group_kernel(
    const float* __restrict__ protos, const int* __restrict__ labels)
{
    const int t = threadIdx.x;
    if (blockIdx.x == 512) {
        #pragma unroll
        for (int i = t; i < N_CLASS; i += 256) g_cnt[i] = 0;
        if (t == 0) { g_nact = 0; g_done = 0; }
        __syncthreads();
        #pragma unroll
        for (int i = t; i < BATCH; i += 256) {
            const int l = labels[i];
            const int pos = atomicAdd(&g_cnt[l], 1);
            if (pos < CAP) g_list[l * CAP + pos] = i;
            if (pos == 0) {
                int a = atomicAdd(&g_nact, 1);
                g_active[a] = l;
            }
        }
        return;
    }
    const int tid = blockIdx.x * 256 + t;
    const int stride = 512 * 256;
    const float4* __restrict__ src = reinterpret_cast<const float4*>(protos);
    __half2* __restrict__ dst = reinterpret_cast<__half2*>(g_protos);
    #pragma unroll 4
    for (int i = tid; i < N_CLASS * FEAT / 4; i += stride) {
        float4 v = src[i];
        dst[2 * i + 0] = __floats2half2_rn(v.x, v.y);
        dst[2 * i + 1] = __floats2half2_rn(v.z, v.w);
    }
    if (tid < N_CLASS) g_rowsum[tid] = 0.0f;
}

// ============================================================================
// Kernel 2: sequential EMA chain for ACTIVE classes only
// ============================================================================
__global__ void __launch_bounds__(256) ema_active_kernel(
    const float* __restrict__ protos,
    const float* __restrict__ feats)
{
    __shared__ int   s_idx[CAP];
    __shared__ float s_red[8];
    __shared__ int   s_c;

    const int t = threadIdx.x;
    if (t == 0) s_c = (blockIdx.x < g_nact) ? g_active[blockIdx.x] : -1;
    __syncthreads();
    const int c = s_c;
    if (c < 0) return;

    const int cnt = min(g_cnt[c], CAP);
    if (t == 0) {
        for (int m = 0; m < cnt; m++) s_idx[m] = g_list[c * CAP + m];
        for (int a = 1; a < cnt; a++) {
            int v = s_idx[a], b = a - 1;
            while (b >= 0 && s_idx[b] > v) { s_idx[b + 1] = s_idx[b]; b--; }
            s_idx[b + 1] = v;
        }
    }
    __syncthreads();

    float4 r = reinterpret_cast<const float4*>(protos)[(size_t)c * (FEAT / 4) + t];
    for (int m = 0; m < cnt; m++) {
        const int i = s_idx[m];
        float4 f = reinterpret_cast<const float4*>(feats)[(size_t)i * (FEAT / 4) + t];
        r.x = r.x * 0.95f + 0.05f * f.x;
        r.y = r.y * 0.95f + 0.05f * f.y;
        r.z = r.z * 0.95f + 0.05f * f.z;
        r.w = r.w * 0.95f + 0.05f * f.w;
        float ss = r.x * r.x + r.y * r.y + r.z * r.z + r.w * r.w;
        #pragma unroll
        for (int o = 16; o > 0; o >>= 1) ss += __shfl_xor_sync(0xffffffffu, ss, o);
        if ((t & 31) == 0) s_red[t >> 5] = ss;
        __syncthreads();
        float tot = s_red[0] + s_red[1] + s_red[2] + s_red[3]
                  + s_red[4] + s_red[5] + s_red[6] + s_red[7];
        float inv = 1.0f / fmaxf(sqrtf(tot), 1e-12f);
        r.x *= inv; r.y *= inv; r.z *= inv; r.w *= inv;
        __syncthreads();
    }

    __half2* dst = reinterpret_cast<__half2*>(g_protos + (size_t)c * FEAT + (size_t)t * 4);
    dst[0] = __floats2half2_rn(r.x, r.y);
    dst[1] = __floats2half2_rn(r.z, r.w);
}

// ============================================================================
// Kernel 3: fused symmetric Gram GEMM (fp16) + exp + row/col sums + finalize.
// mbarrier producer-consumer pipeline (3 slots), warps fully decoupled.
// ============================================================================
__global__ void __launch_bounds__(128, 2) gemm_exp_kernel(float* __restrict__ out)
{
    // decode linear id -> upper-triangle (ti, tj), row-major
    const int id = blockIdx.x;
    int ti = (int)((2.0f * NTILE + 1.0f
                    - sqrtf((2.0f * NTILE + 1.0f) * (2.0f * NTILE + 1.0f) - 8.0f * id))
                   * 0.5f);
    while ((ti + 1) * NTILE - ((ti + 1) * ti) / 2 <= id) ti++;
    while (ti * NTILE - (ti * (ti - 1)) / 2 > id) ti--;
    const int tj = ti + (id - (ti * NTILE - (ti * (ti - 1)) / 2));

    const bool diag   = (ti == tj);
    const int rowBase = ti * TM;
    const int colBase = tj * TN;

    extern __shared__ __align__(1024) char smem[];
    const uint32_t sb   = smem_u32(smem);
    const uint32_t ctrl = sb + CTRL_OFF;       // wr[0..2] at +0,8,16 ; rd[0..2] at +24,32,40

    const int t   = threadIdx.x;          // 0..127
    const int wid = t >> 5;
    const int lid = t & 31;
    const int wr  = wid >> 1;
    const int wc  = wid & 1;

    const __half* __restrict__ P = g_protos;

    if (t == 0) {
        #pragma unroll
        for (int s = 0; s < 3; s++) { mbar_init(ctrl + s * 8, 128); mbar_init(ctrl + 24 + s * 8, 128); }
    }
    __syncthreads();

    // ---- async stage loader (16 x 16B per thread), completion via mbarrier ----
    const int kc = t & 7;
    const int r0 = t >> 3;
    const uint32_t dOffA = r0 * 128 + ((kc ^ (r0 & 7)) << 4);
    const __half* pA0 = P + (size_t)(rowBase + r0) * FEAT + kc * 8;
    const __half* pB0 = P + (size_t)(colBase + r0) * FEAT + kc * 8;

    auto load_stage = [&](int kt) {
        const int slot = kt % 3;
        const uint32_t dA = sb + slot * STAGE_BYTES + dOffA;
        const __half* sA = pA0 + kt * TK;
        const __half* sB = pB0 + kt * TK;
        #pragma unroll
        for (int q = 0; q < 8; q++) {
            asm volatile("cp.async.cg.shared.global [%0], [%1], 16;"
                         :: "r"(dA + q * 2048), "l"(sA + (size_t)q * 16 * FEAT));
            asm volatile("cp.async.cg.shared.global [%0], [%1], 16;"
                         :: "r"(dA + A_BYTES + q * 2048), "l"(sB + (size_t)q * 16 * FEAT));
        }
        cpasync_arrive(ctrl + slot * 8);       // arrive on wr[slot] when copies land
    };

    load_stage(0);
    load_stage(1);
    load_stage(2);

    uint32_t acc[4][8][2];
    #pragma unroll
    for (int mf = 0; mf < 4; mf++)
        #pragma unroll
        for (int nf = 0; nf < 8; nf++) { acc[mf][nf][0] = 0u; acc[mf][nf][1] = 0u; }

    const int lmod16 = lid & 15;
    const int ldiv16 = lid >> 4;
    const int xsw    = lmod16 & 7;
    uint32_t aOff[4], bOff[4];
    #pragma unroll
    for (int mf = 0; mf < 4; mf++) aOff[mf] = (wr * 64 + mf * 16 + lmod16) * 128;
    #pragma unroll
    for (int np = 0; np < 4; np++) bOff[np] = (wc * 64 + np * 16 + lmod16) * 128;

    uint32_t a[2][4][4];
    uint32_t b[2][8][2];

    auto ldfrag = [&](int buf, int slot, int ks) {
        const uint32_t base = sb + slot * STAGE_BYTES;
        const uint32_t sw = (uint32_t)(((ks * 2 + ldiv16) ^ xsw) << 4);
        #pragma unroll
        for (int mf = 0; mf < 4; mf++)
            ldmatrix_x4(a[buf][mf][0], a[buf][mf][1], a[buf][mf][2], a[buf][mf][3],
                        base + aOff[mf] + sw);
        #pragma unroll
        for (int np = 0; np < 4; np++) {
            uint32_t q0, q1, q2, q3;
            ldmatrix_x4(q0, q1, q2, q3, base + A_BYTES + bOff[np] + sw);
            b[buf][np * 2 + 0][0] = q0; b[buf][np * 2 + 0][1] = q2;
            b[buf][np * 2 + 1][0] = q1; b[buf][np * 2 + 1][1] = q3;
        }
    };

    auto mma_step = [&](int buf) {
        #pragma unroll
        for (int mf = 0; mf < 4; mf++)
            #pragma unroll
            for (int nf = 0; nf < 8; nf++)
                mma_f16acc(acc[mf][nf][0], acc[mf][nf][1],
                           a[buf][mf][0], a[buf][mf][1], a[buf][mf][2], a[buf][mf][3],
                           b[buf][nf][0], b[buf][nf][1]);
    };

    // stage 0 ready?
    mbar_wait(ctrl + 0, 0);
    ldfrag(0, 0, 0);

    for (int kt = 0; kt < KTILES; kt++) {
        const int slot = kt % 3;
        // ks0
        ldfrag(1, slot, 1);
        mma_step(0);
        // ks1 (+ mid-kt producer for stage kt+2)
        ldfrag(0, slot, 2);
        if (kt >= 1 && kt <= 13) {
            const int ps = (kt - 1) % 3;                 // slot being recycled
            mbar_wait(ctrl + 24 + ps * 8, (uint32_t)(((kt - 1) / 3) & 1));  // rd[ps] done
            load_stage(kt + 2);
        }
        mma_step(1);
        // ks2 (last read of this slot -> arrive rd[slot])
        ldfrag(1, slot, 3);
        mbar_arrive(ctrl + 24 + slot * 8);
        mma_step(0);
        // ks3 (+ prefetch next kt's ks0 fragments)
        if (kt < KTILES - 1) {
            const int ns = (kt + 1) % 3;
            mbar_wait(ctrl + ns * 8, (uint32_t)(((kt + 1) / 3) & 1));       // wr[ns] done
            ldfrag(0, ns, 0);
        }
        mma_step(1);
    }

    // ---- epilogue: exp(10*x), row sums + (off-diag) butterfly column sums ----
    float* srow = reinterpret_cast<float*>(smem);        // [128]
    float* scol = srow + 128;                            // [128]
    __syncthreads();
    srow[t] = 0.0f;
    srow[t + 128] = 0.0f;
    __syncthreads();

    const int g  = lid >> 2;
    const int tg = lid & 3;

    float cs[8][2];
    #pragma unroll
    for (int nf = 0; nf < 8; nf++) { cs[nf][0] = 0.0f; cs[nf][1] = 0.0f; }

    #pragma unroll
    for (int mf = 0; mf < 4; mf++) {
        float rs0 = 0.0f, rs1 = 0.0f;
        const int gr0 = rowBase + wr * 64 + mf * 16 + g;
        const int gr1 = gr0 + 8;
        #pragma unroll
        for (int nf = 0; nf < 8; nf++) {
            float2 lo = __half22float2(*reinterpret_cast<__half2*>(&acc[mf][nf][0]));
            float2 hi = __half22float2(*reinterpret_cast<__half2*>(&acc[mf][nf][1]));
            float e0 = __expf(lo.x * 10.0f);
            float e1 = __expf(lo.y * 10.0f);
            float e2 = __expf(hi.x * 10.0f);
            float e3 = __expf(hi.y * 10.0f);
            if (diag) {
                const int gc0 = colBase + wc * 64 + nf * 8 + 2 * tg;
                const int gc1 = gc0 + 1;
                if (gr0 == gc0) e0 = 0.0f;
                if (gr0 == gc1) e1 = 0.0f;
                if (gr1 == gc0) e2 = 0.0f;
                if (gr1 == gc1) e3 = 0.0f;
            }
            rs0 += e0 + e1;
            rs1 += e2 + e3;
            cs[nf][0] += e0 + e2;
            cs[nf][1] += e1 + e3;
        }
        rs0 += __shfl_xor_sync(0xffffffffu, rs0, 1);
        rs0 += __shfl_xor_sync(0xffffffffu, rs0, 2);
        rs1 += __shfl_xor_sync(0xffffffffu, rs1, 1);
        rs1 += __shfl_xor_sync(0xffffffffu, rs1, 2);
        if (tg == 0) {
            atomicAdd(&srow[wr * 64 + mf * 16 + g],     rs0);
            atomicAdd(&srow[wr * 64 + mf * 16 + g + 8], rs1);
        }
    }
    if (!diag) {
        #pragma unroll
        for (int nf = 0; nf < 8; nf++) {
            #pragma unroll
            for (int h = 0; h < 2; h++) {
                float v = cs[nf][h];
                v += __shfl_xor_sync(0xffffffffu, v, 4);
                v += __shfl_xor_sync(0xffffffffu, v, 8);
                v += __shfl_xor_sync(0xffffffffu, v, 16);
                if (g == 0)
                    atomicAdd(&scol[wc * 64 + nf * 8 + 2 * tg + h], v);
            }
        }
    }
    __syncthreads();
    atomicAdd(&g_rowsum[rowBase + t], srow[t]);
    if (!diag) atomicAdd(&g_rowsum[colBase + t], scol[t]);

    // ---- last CTA computes the loss ----
    __threadfence();
    __syncthreads();
    __shared__ int s_last;
    if (t == 0) s_last = (atomicAdd(&g_done, 1) == NTRI - 1) ? 1 : 0;
    __syncthreads();
    if (s_last) {
        __threadfence();
        float acc2 = 0.0f;
        for (int i = t; i < N_CLASS; i += 128)
            acc2 += logf(g_rowsum[i] * (1.0f / (float)(N_CLASS - 1)));
        #pragma unroll
        for (int o = 16; o > 0; o >>= 1) acc2 += __shfl_xor_sync(0xffffffffu, acc2, o);
        if (lid == 0) srow[wid] = acc2;
        __syncthreads();
        if (t == 0)
            out[0] = (srow[0] + srow[1] + srow[2] + srow[3]) / (float)N_CLASS;
    }
}

// ============================================================================
extern "C" void kernel_launch(void* const* d_in, const int* in_sizes, int n_in,
                              void* d_out, int out_size)
{
    const float* features   = nullptr;
    const int*   labels     = nullptr;
    const float* prototypes = nullptr;
    for (int k = 0; k < n_in; k++) {
        if      (in_sizes[k] == BATCH)          labels     = (const int*)d_in[k];
        else if (in_sizes[k] == BATCH * FEAT)   features   = (const float*)d_in[k];
        else if (in_sizes[k] == N_CLASS * FEAT) prototypes = (const float*)d_in[k];
    }
    float* out = (float*)d_out;

    static bool attr_done = false;
    if (!attr_done) {
        cudaFuncSetAttribute(gemm_exp_kernel,
                             cudaFuncAttributeMaxDynamicSharedMemorySize, SMEM_TOTAL);
        attr_done = true;
    }

    convert_group_kernel<<<513, 256>>>(prototypes, labels);
    ema_active_kernel<<<BATCH, 256>>>(prototypes, features);
    gemm_exp_kernel<<<NTRI, 128, SMEM_TOTAL>>>(out);
    (void)out_size;
}

// round 8
// speedup vs baseline: 1.1997x; 1.1050x over previous
#include <cuda_runtime.h>
#include <cuda_fp16.h>
#include <cstdint>
#include <cstddef>

#define N_CLASS 8192
#define FEAT    1024
#define BATCH   1024

#define TM 128
#define TN 128
#define TK 64
#define KTILES (FEAT / TK)        // 16
#define A_BYTES (TM * 128)        // 16 KB (128 rows x 128B)
#define B_BYTES (TN * 128)        // 16 KB
#define STAGE_BYTES (A_BYTES + B_BYTES)   // 32 KB
#define CTRL_OFF (2 * STAGE_BYTES)        // 64 KB
#define SMEM_TOTAL (CTRL_OFF + 128)

#define NTILE (N_CLASS / TM)                  // 64
#define NTRI  (NTILE * (NTILE + 1) / 2)       // 2080 upper-triangle tiles
#define CAP 32

// ---------------- device scratch (no allocations allowed) ----------------
__device__ __half g_protos[(size_t)N_CLASS * FEAT];  // 16 MB fp16 protos
__device__ float  g_rowsum[N_CLASS];
__device__ int    g_cnt[N_CLASS];
__device__ int    g_list[N_CLASS * CAP];
__device__ int    g_active[BATCH];
__device__ int    g_nact;
__device__ int    g_done;

// ---------------- helpers ----------------
__device__ __forceinline__ uint32_t smem_u32(const void* p) {
    uint32_t a;
    asm("{ .reg .u64 t; cvta.to.shared.u64 t, %1; cvt.u32.u64 %0, t; }" : "=r"(a) : "l"(p));
    return a;
}
__device__ __forceinline__ void ldmatrix_x4(uint32_t& r0, uint32_t& r1,
                                            uint32_t& r2, uint32_t& r3, uint32_t addr) {
    asm volatile("ldmatrix.sync.aligned.m8n8.x4.shared.b16 {%0,%1,%2,%3}, [%4];"
                 : "=r"(r0), "=r"(r1), "=r"(r2), "=r"(r3) : "r"(addr));
}
__device__ __forceinline__ void mma_f16acc(uint32_t& c0, uint32_t& c1,
                                           uint32_t a0, uint32_t a1, uint32_t a2, uint32_t a3,
                                           uint32_t b0, uint32_t b1) {
    asm volatile(
        "mma.sync.aligned.m16n8k16.row.col.f16.f16.f16.f16 "
        "{%0,%1}, {%2,%3,%4,%5}, {%6,%7}, {%0,%1};"
        : "+r"(c0), "+r"(c1)
        : "r"(a0), "r"(a1), "r"(a2), "r"(a3), "r"(b0), "r"(b1));
}
__device__ __forceinline__ void mbar_init(uint32_t mbar, uint32_t cnt) {
    asm volatile("mbarrier.init.shared.b64 [%0], %1;" :: "r"(mbar), "r"(cnt) : "memory");
}
__device__ __forceinline__ void mbar_arrive(uint32_t mbar) {
    asm volatile("mbarrier.arrive.shared.b64 _, [%0];" :: "r"(mbar) : "memory");
}
__device__ __forceinline__ void cpasync_arrive(uint32_t mbar) {
    asm volatile("cp.async.mbarrier.arrive.noinc.shared.b64 [%0];" :: "r"(mbar) : "memory");
}
__device__ __forceinline__ void mbar_wait(uint32_t mbar, uint32_t parity) {
    asm volatile(
        "{\n\t.reg .pred P;\n\t"
        "W_%=:\n\t"
        "mbarrier.try_wait.parity.acquire.cta.shared::cta.b64 P, [%0], %1, 0x989680;\n\t"
        "@!P bra W_%=;\n\t}"
        :: "r"(mbar), "r"(parity) : "memory");
}

// ============================================================================
// Kernel 1: fused fp32->fp16 convert (blocks 0..2047) + label grouping (block 2048)
// ============================================================================
__global__ void __launch_bounds__(256) convert_group_kernel(
    const float* __restrict__ protos, const int* __restrict__ labels)
{
    const int t = threadIdx.x;
    if (blockIdx.x == 2048) {
        #pragma unroll
        for (int i = t; i < N_CLASS; i += 256) g_cnt[i] = 0;
        if (t == 0) { g_nact = 0; g_done = 0; }
        __syncthreads();
        #pragma unroll
        for (int i = t; i < BATCH; i += 256) {
            const int l = labels[i];
            const int pos = atomicAdd(&g_cnt[l], 1);
            if (pos < CAP) g_list[l * CAP + pos] = i;
            if (pos == 0) {
                int a = atomicAdd(&g_nact, 1);
                g_active[a] = l;
            }
        }
        return;
    }
    // 2048 blocks x 256 threads x 4 float4 = full 8192x1024 tensor
    const int tid = blockIdx.x * 256 + t;
    const float4* __restrict__ src = reinterpret_cast<const float4*>(protos);
    __half2* __restrict__ dst = reinterpret_cast<__half2*>(g_protos);
    float4 v0 = src[tid];
    float4 v1 = src[tid + 524288];
    float4 v2 = src[tid + 1048576];
    float4 v3 = src[tid + 1572864];
    dst[2 * tid + 0]             = __floats2half2_rn(v0.x, v0.y);
    dst[2 * tid + 1]             = __floats2half2_rn(v0.z, v0.w);
    dst[2 * (tid + 524288) + 0]  = __floats2half2_rn(v1.x, v1.y);
    dst[2 * (tid + 524288) + 1]  = __floats2half2_rn(v1.z, v1.w);
    dst[2 * (tid + 1048576) + 0] = __floats2half2_rn(v2.x, v2.y);
    dst[2 * (tid + 1048576) + 1] = __floats2half2_rn(v2.z, v2.w);
    dst[2 * (tid + 1572864) + 0] = __floats2half2_rn(v3.x, v3.y);
    dst[2 * (tid + 1572864) + 1] = __floats2half2_rn(v3.z, v3.w);
    if (tid < N_CLASS) g_rowsum[tid] = 0.0f;
}

// ============================================================================
// Kernel 2: sequential EMA chain for ACTIVE classes only
// ============================================================================
__global__ void __launch_bounds__(256) ema_active_kernel(
    const float* __restrict__ protos,
    const float* __restrict__ feats)
{
    __shared__ int   s_idx[CAP];
    __shared__ float s_red[8];
    __shared__ int   s_c;

    const int t = threadIdx.x;
    if (t == 0) s_c = (blockIdx.x < g_nact) ? g_active[blockIdx.x] : -1;
    __syncthreads();
    const int c = s_c;
    if (c < 0) return;

    const int cnt = min(g_cnt[c], CAP);
    if (t == 0) {
        for (int m = 0; m < cnt; m++) s_idx[m] = g_list[c * CAP + m];
        for (int a = 1; a < cnt; a++) {
            int v = s_idx[a], b = a - 1;
            while (b >= 0 && s_idx[b] > v) { s_idx[b + 1] = s_idx[b]; b--; }
            s_idx[b + 1] = v;
        }
    }
    __syncthreads();

    float4 r = reinterpret_cast<const float4*>(protos)[(size_t)c * (FEAT / 4) + t];
    for (int m = 0; m < cnt; m++) {
        const int i = s_idx[m];
        float4 f = reinterpret_cast<const float4*>(feats)[(size_t)i * (FEAT / 4) + t];
        r.x = r.x * 0.95f + 0.05f * f.x;
        r.y = r.y * 0.95f + 0.05f * f.y;
        r.z = r.z * 0.95f + 0.05f * f.z;
        r.w = r.w * 0.95f + 0.05f * f.w;
        float ss = r.x * r.x + r.y * r.y + r.z * r.z + r.w * r.w;
        #pragma unroll
        for (int o = 16; o > 0; o >>= 1) ss += __shfl_xor_sync(0xffffffffu, ss, o);
        if ((t & 31) == 0) s_red[t >> 5] = ss;
        __syncthreads();
        float tot = s_red[0] + s_red[1] + s_red[2] + s_red[3]
                  + s_red[4] + s_red[5] + s_red[6] + s_red[7];
        float inv = 1.0f / fmaxf(sqrtf(tot), 1e-12f);
        r.x *= inv; r.y *= inv; r.z *= inv; r.w *= inv;
        __syncthreads();
    }

    __half2* dst = reinterpret_cast<__half2*>(g_protos + (size_t)c * FEAT + (size_t)t * 4);
    dst[0] = __floats2half2_rn(r.x, r.y);
    dst[1] = __floats2half2_rn(r.z, r.w);
}

// ============================================================================
// Kernel 3: fused symmetric Gram GEMM (fp16) + exp + row/col sums + finalize.
// 2-slot mbarrier producer-consumer pipeline, 3 CTAs/SM (3 warps/SMSP).
// ============================================================================
__global__ void __launch_bounds__(128, 3) gemm_exp_kernel(float* __restrict__ out)
{
    // decode linear id -> upper-triangle (ti, tj), row-major
    const int id = blockIdx.x;
    int ti = (int)((2.0f * NTILE + 1.0f
                    - sqrtf((2.0f * NTILE + 1.0f) * (2.0f * NTILE + 1.0f) - 8.0f * id))
                   * 0.5f);
    while ((ti + 1) * NTILE - ((ti + 1) * ti) / 2 <= id) ti++;
    while (ti * NTILE - (ti * (ti - 1)) / 2 > id) ti--;
    const int tj = ti + (id - (ti * NTILE - (ti * (ti - 1)) / 2));

    const bool diag   = (ti == tj);
    const int rowBase = ti * TM;
    const int colBase = tj * TN;

    extern __shared__ __align__(1024) char smem[];
    const uint32_t sb   = smem_u32(smem);
    const uint32_t ctrl = sb + CTRL_OFF;   // wr[0],wr[1] at +0,+8 ; rd[0],rd[1] at +16,+24

    const int t   = threadIdx.x;          // 0..127
    const int wid = t >> 5;
    const int lid = t & 31;
    const int wr  = wid >> 1;
    const int wc  = wid & 1;

    const __half* __restrict__ P = g_protos;

    if (t == 0) {
        #pragma unroll
        for (int s = 0; s < 2; s++) { mbar_init(ctrl + s * 8, 128); mbar_init(ctrl + 16 + s * 8, 128); }
    }
    __syncthreads();

    // ---- async stage loader (16 x 16B per thread), completion via mbarrier ----
    const int kc = t & 7;
    const int r0 = t >> 3;
    const uint32_t dOffA = r0 * 128 + ((kc ^ (r0 & 7)) << 4);
    const __half* pA0 = P + (size_t)(rowBase + r0) * FEAT + kc * 8;
    const __half* pB0 = P + (size_t)(colBase + r0) * FEAT + kc * 8;

    auto load_stage = [&](int kt) {
        const int slot = kt & 1;
        const uint32_t dA = sb + slot * STAGE_BYTES + dOffA;
        const __half* sA = pA0 + kt * TK;
        const __half* sB = pB0 + kt * TK;
        #pragma unroll
        for (int q = 0; q < 8; q++) {
            asm volatile("cp.async.cg.shared.global [%0], [%1], 16;"
                         :: "r"(dA + q * 2048), "l"(sA + (size_t)q * 16 * FEAT));
            asm volatile("cp.async.cg.shared.global [%0], [%1], 16;"
                         :: "r"(dA + A_BYTES + q * 2048), "l"(sB + (size_t)q * 16 * FEAT));
        }
        cpasync_arrive(ctrl + slot * 8);
    };

    load_stage(0);
    load_stage(1);

    uint32_t acc[4][8][2];
    #pragma unroll
    for (int mf = 0; mf < 4; mf++)
        #pragma unroll
        for (int nf = 0; nf < 8; nf++) { acc[mf][nf][0] = 0u; acc[mf][nf][1] = 0u; }

    const int lmod16 = lid & 15;
    const int ldiv16 = lid >> 4;
    const int xsw    = lmod16 & 7;
    uint32_t aOff[4], bOff[4];
    #pragma unroll
    for (int mf = 0; mf < 4; mf++) aOff[mf] = (wr * 64 + mf * 16 + lmod16) * 128;
    #pragma unroll
    for (int np = 0; np < 4; np++) bOff[np] = (wc * 64 + np * 16 + lmod16) * 128;

    uint32_t a[2][4][4];
    uint32_t b[2][8][2];

    auto ldfrag = [&](int buf, int slot, int ks) {
        const uint32_t base = sb + slot * STAGE_BYTES;
        const uint32_t sw = (uint32_t)(((ks * 2 + ldiv16) ^ xsw) << 4);
        #pragma unroll
        for (int mf = 0; mf < 4; mf++)
            ldmatrix_x4(a[buf][mf][0], a[buf][mf][1], a[buf][mf][2], a[buf][mf][3],
                        base + aOff[mf] + sw);
        #pragma unroll
        for (int np = 0; np < 4; np++) {
            uint32_t q0, q1, q2, q3;
            ldmatrix_x4(q0, q1, q2, q3, base + A_BYTES + bOff[np] + sw);
            b[buf][np * 2 + 0][0] = q0; b[buf][np * 2 + 0][1] = q2;
            b[buf][np * 2 + 1][0] = q1; b[buf][np * 2 + 1][1] = q3;
        }
    };

    auto mma_step = [&](int buf) {
        #pragma unroll
        for (int mf = 0; mf < 4; mf++)
            #pragma unroll
            for (int nf = 0; nf < 8; nf++)
                mma_f16acc(acc[mf][nf][0], acc[mf][nf][1],
                           a[buf][mf][0], a[buf][mf][1], a[buf][mf][2], a[buf][mf][3],
                           b[buf][nf][0], b[buf][nf][1]);
    };

    mbar_wait(ctrl + 0, 0);       // stage 0 written
    ldfrag(0, 0, 0);

    for (int kt = 0; kt < KTILES; kt++) {
        const int slot = kt & 1;
        ldfrag(1, slot, 1);
        mma_step(0);
        ldfrag(0, slot, 2);
        mma_step(1);
        ldfrag(1, slot, 3);
        mbar_arrive(ctrl + 16 + slot * 8);          // done reading this slot
        mma_step(0);
        if (kt <= KTILES - 3) {
            mbar_wait(ctrl + 16 + slot * 8, (uint32_t)((kt >> 1) & 1));   // all warps done
            load_stage(kt + 2);
        }
        mma_step(1);
        if (kt < KTILES - 1) {
            const int ns = slot ^ 1;
            mbar_wait(ctrl + ns * 8, (uint32_t)(((kt + 1) >> 1) & 1));    // next stage written
            ldfrag(0, ns, 0);
        }
    }

    // ---- epilogue: exp(10*x), row sums + (off-diag) butterfly column sums ----
    float* srow = reinterpret_cast<float*>(smem);        // [128]
    float* scol = srow + 128;                            // [128]
    __syncthreads();
    srow[t] = 0.0f;
    srow[t + 128] = 0.0f;
    __syncthreads();

    const int g  = lid >> 2;
    const int tg = lid & 3;

    float cs[8][2];
    #pragma unroll
    for (int nf = 0; nf < 8; nf++) { cs[nf][0] = 0.0f; cs[nf][1] = 0.0f; }

    #pragma unroll
    for (int mf = 0; mf < 4; mf++) {
        float rs0 = 0.0f, rs1 = 0.0f;
        const int gr0 = rowBase + wr * 64 + mf * 16 + g;
        const int gr1 = gr0 + 8;
        #pragma unroll
        for (int nf = 0; nf < 8; nf++) {
            float2 lo = __half22float2(*reinterpret_cast<__half2*>(&acc[mf][nf][0]));
            float2 hi = __half22float2(*reinterpret_cast<__half2*>(&acc[mf][nf][1]));
            float e0 = __expf(lo.x * 10.0f);
            float e1 = __expf(lo.y * 10.0f);
            float e2 = __expf(hi.x * 10.0f);
            float e3 = __expf(hi.y * 10.0f);
            if (diag) {
                const int gc0 = colBase + wc * 64 + nf * 8 + 2 * tg;
                const int gc1 = gc0 + 1;
                if (gr0 == gc0) e0 = 0.0f;
                if (gr0 == gc1) e1 = 0.0f;
                if (gr1 == gc0) e2 = 0.0f;
                if (gr1 == gc1) e3 = 0.0f;
            }
            rs0 += e0 + e1;
            rs1 += e2 + e3;
            cs[nf][0] += e0 + e2;
            cs[nf][1] += e1 + e3;
        }
        rs0 += __shfl_xor_sync(0xffffffffu, rs0, 1);
        rs0 += __shfl_xor_sync(0xffffffffu, rs0, 2);
        rs1 += __shfl_xor_sync(0xffffffffu, rs1, 1);
        rs1 += __shfl_xor_sync(0xffffffffu, rs1, 2);
        if (tg == 0) {
            atomicAdd(&srow[wr * 64 + mf * 16 + g],     rs0);
            atomicAdd(&srow[wr * 64 + mf * 16 + g + 8], rs1);
        }
    }
    if (!diag) {
        #pragma unroll
        for (int nf = 0; nf < 8; nf++) {
            #pragma unroll
            for (int h = 0; h < 2; h++) {
                float v = cs[nf][h];
                v += __shfl_xor_sync(0xffffffffu, v, 4);
                v += __shfl_xor_sync(0xffffffffu, v, 8);
                v += __shfl_xor_sync(0xffffffffu, v, 16);
                if (g == 0)
                    atomicAdd(&scol[wc * 64 + nf * 8 + 2 * tg + h], v);
            }
        }
    }
    __syncthreads();
    atomicAdd(&g_rowsum[rowBase + t], srow[t]);
    if (!diag) atomicAdd(&g_rowsum[colBase + t], scol[t]);

    // ---- last CTA computes the loss ----
    __threadfence();
    __syncthreads();
    __shared__ int s_last;
    if (t == 0) s_last = (atomicAdd(&g_done, 1) == NTRI - 1) ? 1 : 0;
    __syncthreads();
    if (s_last) {
        __threadfence();
        float acc2 = 0.0f;
        for (int i = t; i < N_CLASS; i += 128)
            acc2 += logf(g_rowsum[i] * (1.0f / (float)(N_CLASS - 1)));
        #pragma unroll
        for (int o = 16; o > 0; o >>= 1) acc2 += __shfl_xor_sync(0xffffffffu, acc2, o);
        if (lid == 0) srow[wid] = acc2;
        __syncthreads();
        if (t == 0)
            out[0] = (srow[0] + srow[1] + srow[2] + srow[3]) / (float)N_CLASS;
    }
}

// ============================================================================
extern "C" void kernel_launch(void* const* d_in, const int* in_sizes, int n_in,
                              void* d_out, int out_size)
{
    const float* features   = nullptr;
    const int*   labels     = nullptr;
    const float* prototypes = nullptr;
    for (int k = 0; k < n_in; k++) {
        if      (in_sizes[k] == BATCH)          labels     = (const int*)d_in[k];
        else if (in_sizes[k] == BATCH * FEAT)   features   = (const float*)d_in[k];
        else if (in_sizes[k] == N_CLASS * FEAT) prototypes = (const float*)d_in[k];
    }
    float* out = (float*)d_out;

    static bool attr_done = false;
    if (!attr_done) {
        cudaFuncSetAttribute(gemm_exp_kernel,
                             cudaFuncAttributeMaxDynamicSharedMemorySize, SMEM_TOTAL);
        attr_done = true;
    }

    convert_group_kernel<<<2049, 256>>>(prototypes, labels);
    ema_active_kernel<<<BATCH, 256>>>(prototypes, features);
    gemm_exp_kernel<<<NTRI, 128, SMEM_TOTAL>>>(out);
    (void)out_size;
}